// round 5
// baseline (speedup 1.0000x reference)
#include <cuda_runtime.h>
#include <cuda_fp16.h>

// Bilinear flow warp via fp16 overlapped-pair SMEM tiles.
//   img: [B=8, C=16, H=512, W=512] f32
//   flo: [B=8, 2,   H=512, W=512] f32
//   out: [B=8, C=16, H=512, W=512] f32
//
// Block = one (b, 16-row) full-width strip. Per channel, TROWS=24 rows are
// staged in SMEM as __half2 pairs tile[r][x] = (v[x], v[x+1]), so a single
// aligned 4-byte LDS fetches both x-neighbors of any gather. Weights stay
// fp32-exact (u16.16 packed); only texels are fp16 (rel err <= 2^-11).
// Pixels whose y-neighbors miss the halo (P ~ 6e-5) use exact global loads.

#define B_    8
#define C_    16
#define H_    512
#define W_    512
#define HW_   (H_ * W_)
#define TY    16
#define HALO  4
#define TROWS (TY + 2 * HALO)          // 24
#define THREADS 512
#define FB_BIT  (1 << 22)

__device__ __forceinline__ unsigned h2_as_u32(__half2 h) {
    return *reinterpret_cast<unsigned*>(&h);
}

__global__ __launch_bounds__(THREADS, 2) void warp_bilinear_kernel(
    const float* __restrict__ img,
    const float* __restrict__ flo,
    float* __restrict__ out)
{
    __shared__ __half2 tile[TROWS * W_];   // 24*512*4B = 48 KB

    const int bx = blockIdx.x;             // 0 .. 255
    const int b  = bx >> 5;                // 32 strips per batch
    const int h0 = (bx & 31) * TY;
    const int w  = threadIdx.x;            // one column per thread
    const int lane = w & 31;
    const int row_lo = h0 - HALO;

    // ---- Prologue: per-pixel geometry, packed 2 regs/pixel ----
    // pk: x0 | field2<<10 | dx<<20 | dy<<21 | fb<<22
    //     field2 = tile-row (if !fb) else global y0
    // wq: xw(u16) | yw(u16)<<16  (fixed-point weights, err 1.5e-5)
    int pk[TY];
    unsigned wq[TY];

    const int flo_b = (b * 2) * HW_;
    #pragma unroll
    for (int i = 0; i < TY; i++) {
        int h = h0 + i;
        float fx = __ldg(flo + flo_b + h * W_ + w);
        float fy = __ldg(flo + flo_b + HW_ + h * W_ + w);

        float px = (float)w + fx;
        float py = (float)h + fy;
        float x0f = floorf(px);
        float y0f = floorf(py);
        float xw = px - x0f;               // weights from UNclamped floor
        float yw = py - y0f;
        wq[i] = __float2uint_rn(xw * 65535.0f)
              | (__float2uint_rn(yw * 65535.0f) << 16);

        int x0 = (int)fminf(fmaxf(x0f,        0.0f), (float)(W_ - 1));
        int x1 = (int)fminf(fmaxf(x0f + 1.0f, 0.0f), (float)(W_ - 1));
        int y0 = (int)fminf(fmaxf(y0f,        0.0f), (float)(H_ - 1));
        int y1 = (int)fminf(fmaxf(y0f + 1.0f, 0.0f), (float)(H_ - 1));

        int dx = x1 - x0;
        int dy = y1 - y0;
        int fb = (y0 < row_lo) || (y1 > row_lo + TROWS - 1);
        int f2 = fb ? y0 : (y0 - row_lo);
        pk[i] = x0 | (f2 << 10) | (dx << 20) | (dy << 21) | (fb ? FB_BIT : 0);
    }

    const float inv16 = 1.0f / 65535.0f;

    for (int c = 0; c < C_; c++) {
        const float* plane = img + ((size_t)(b * C_ + c)) * HW_;

        __syncthreads();                   // protect tile from previous reads
        // ---- Fill: 3072 float4 slots = 24 rows x 128, coalesced ----
        #pragma unroll
        for (int k = 0; k < 6; k++) {
            int f    = threadIdx.x + k * THREADS;  // 0..3071
            int r    = f >> 7;                     // 128 float4 per row
            int col4 = f & 127;
            int col  = col4 << 2;
            int gy   = min(max(row_lo + r, 0), H_ - 1);
            const float* rp = plane + gy * W_;
            float4 v = __ldg((const float4*)(rp + col));
            // v4 = v[col+4]: next lane's v.x within the same row
            float v4 = __shfl_down_sync(0xffffffffu, v.x, 1);
            if (col4 == 127)      v4 = v.w;        // x=511 pair clamps
            else if (lane == 31)  v4 = __ldg(rp + col + 4);

            __half2 p0 = __floats2half2_rn(v.x, v.y);
            __half2 p1 = __floats2half2_rn(v.y, v.z);
            __half2 p2 = __floats2half2_rn(v.z, v.w);
            __half2 p3 = __floats2half2_rn(v.w, v4);
            uint4 pkt = make_uint4(h2_as_u32(p0), h2_as_u32(p1),
                                   h2_as_u32(p2), h2_as_u32(p3));
            *(uint4*)&tile[r * W_ + col] = pkt;
        }
        __syncthreads();

        // ---- Gather + blend + store ----
        float* oplane = out + ((size_t)(b * C_ + c)) * HW_;
        #pragma unroll
        for (int i = 0; i < TY; i++) {
            int p  = pk[i];
            int x0 = p & 1023;
            int f2 = (p >> 10) & 1023;
            int dx = (p >> 20) & 1;
            int dy = (p >> 21) & 1;

            float Ia, Ib, Ic, Id;
            if (!(p & FB_BIT)) {
                float2 t0 = __half22float2(tile[f2 * W_ + x0]);
                float2 t1 = __half22float2(tile[(f2 + dy) * W_ + x0]);
                Ia = t0.x;  Ic = dx ? t0.y : t0.x;
                Ib = t1.x;  Id = dx ? t1.y : t1.x;
            } else {
                const float* g  = plane + f2 * W_ + x0;   // f2 = global y0
                const float* g1 = g + dy * W_;
                Ia = __ldg(g);  Ic = __ldg(g + dx);
                Ib = __ldg(g1); Id = __ldg(g1 + dx);
            }

            unsigned q = wq[i];
            float xw = (float)(q & 0xffffu) * inv16;
            float yw = (float)(q >> 16)     * inv16;
            float wa = (1.0f - xw) * (1.0f - yw);
            float wb = (1.0f - xw) * yw;
            float wc = xw * (1.0f - yw);
            float wd = xw * yw;

            float r = wa * Ia;
            r = fmaf(wb, Ib, r);
            r = fmaf(wc, Ic, r);
            r = fmaf(wd, Id, r);
            oplane[(h0 + i) * W_ + w] = r;
        }
    }
}

extern "C" void kernel_launch(void* const* d_in, const int* in_sizes, int n_in,
                              void* d_out, int out_size)
{
    const float* img = (const float*)d_in[0];
    const float* flo = (const float*)d_in[1];
    float* out = (float*)d_out;

    const int blocks = B_ * (H_ / TY);   // 256
    warp_bilinear_kernel<<<blocks, THREADS>>>(img, flo, out);
}

// round 7
// speedup vs baseline: 2.4211x; 2.4211x over previous
#include <cuda_runtime.h>
#include <cstdint>

// Bilinear flow warp: exact fp32 SMEM row-strip tiles, cp.async double-buffered
// over the channel loop so fill latency hides under the previous channel's
// gather phase. 64KB dynamic SMEM (2 x 32KB buffers).
//   img: [B=8, C=16, H=512, W=512] f32
//   flo: [B=8, 2,   H=512, W=512] f32
//   out: [B=8, C=16, H=512, W=512] f32

#define B_    8
#define C_    16
#define H_    512
#define W_    512
#define HW_   (H_ * W_)
#define TY    8
#define HALO  4
#define TROWS (TY + 2 * HALO)          // 16 rows resident per buffer
#define THREADS 512
#define FB_BIT  (1 << 22)
#define SMEM_BYTES (2 * TROWS * W_ * 4)   // 65536

__device__ __forceinline__ void cp_async16(uint32_t smem_addr, const void* gptr) {
    asm volatile("cp.async.cg.shared.global [%0], [%1], 16;\n"
                 :: "r"(smem_addr), "l"(gptr) : "memory");
}
__device__ __forceinline__ void cp_commit() {
    asm volatile("cp.async.commit_group;\n" ::: "memory");
}
template <int N>
__device__ __forceinline__ void cp_wait() {
    asm volatile("cp.async.wait_group %0;\n" :: "n"(N) : "memory");
}

__global__ __launch_bounds__(THREADS, 2) void warp_bilinear_kernel(
    const float* __restrict__ img,
    const float* __restrict__ flo,
    float* __restrict__ out)
{
    extern __shared__ float tile[];         // [2][TROWS * W_]

    const int bx = blockIdx.x;              // 0 .. 511
    const int b  = bx >> 6;                 // 64 strips per batch
    const int h0 = (bx & 63) * TY;
    const int w  = threadIdx.x;             // one column per thread
    const int row_lo = h0 - HALO;

    // ---- Per-pixel geometry (channel-invariant), 24 regs ----
    float xw[TY], yw[TY];
    int   pk[TY];                           // x0 | f2<<10 | dx<<20 | dy<<21 | fb<<22

    const int flo_b = (b * 2) * HW_;
    #pragma unroll
    for (int i = 0; i < TY; i++) {
        int h = h0 + i;
        float fx = __ldg(flo + flo_b + h * W_ + w);
        float fy = __ldg(flo + flo_b + HW_ + h * W_ + w);

        float px = (float)w + fx;
        float py = (float)h + fy;
        float x0f = floorf(px);
        float y0f = floorf(py);
        xw[i] = px - x0f;                   // weights from UNclamped floor
        yw[i] = py - y0f;

        int x0 = (int)fminf(fmaxf(x0f,        0.0f), (float)(W_ - 1));
        int x1 = (int)fminf(fmaxf(x0f + 1.0f, 0.0f), (float)(W_ - 1));
        int y0 = (int)fminf(fmaxf(y0f,        0.0f), (float)(H_ - 1));
        int y1 = (int)fminf(fmaxf(y0f + 1.0f, 0.0f), (float)(H_ - 1));

        int dx = x1 - x0;
        int dy = y1 - y0;
        int fb = (y0 < row_lo) || (y1 > row_lo + TROWS - 1);
        int f2 = fb ? y0 : (y0 - row_lo);
        pk[i] = x0 | (f2 << 10) | (dx << 20) | (dy << 21) | (fb ? FB_BIT : 0);
    }

    const float* bimg = img + (size_t)b * C_ * HW_;

    // ---- Fill helper: channel ch -> buffer buf, 4 x cp.async.cg(16B)/thread ----
    auto prefetch = [&](int ch, int buf) {
        const float* plane = bimg + (size_t)ch * HW_;
        float* tb = tile + buf * (TROWS * W_);
        #pragma unroll
        for (int k = 0; k < 4; k++) {
            int f   = threadIdx.x + k * THREADS;    // float4 slot 0..2047
            int r   = f >> 7;                       // 128 slots per row
            int col = (f & 127) << 2;
            int gy  = min(max(row_lo + r, 0), H_ - 1);
            uint32_t sa = (uint32_t)__cvta_generic_to_shared(tb + r * W_ + col);
            cp_async16(sa, plane + gy * W_ + col);
        }
        cp_commit();
    };

    prefetch(0, 0);

    for (int c = 0; c < C_; c++) {
        if (c + 1 < C_) {
            prefetch(c + 1, (c + 1) & 1);   // buf (c+1)&1 free: gathers of c-1 done
            cp_wait<1>();                   // retire group c (buf c&1 filled)
        } else {
            cp_wait<0>();
        }
        __syncthreads();                    // publish fills to all warps

        const float* plane  = bimg + (size_t)c * HW_;
        float*       oplane = out + ((size_t)(b * C_ + c)) * HW_;
        const float* tbuf   = tile + (c & 1) * (TROWS * W_);

        #pragma unroll
        for (int i = 0; i < TY; i++) {
            int p  = pk[i];
            int x0 = p & 1023;
            int f2 = (p >> 10) & 1023;
            int dx = (p >> 20) & 1;
            int dy = (p >> 21) & 1;

            float Ia, Ib, Ic, Id;
            if (!(p & FB_BIT)) {
                int base  = f2 * W_ + x0;
                int base1 = base + dy * W_;
                Ia = tbuf[base];
                Ic = tbuf[base + dx];
                Ib = tbuf[base1];
                Id = tbuf[base1 + dx];
            } else {                         // f2 = global y0 here
                const float* g  = plane + f2 * W_ + x0;
                const float* g1 = g + dy * W_;
                Ia = __ldg(g);  Ic = __ldg(g + dx);
                Ib = __ldg(g1); Id = __ldg(g1 + dx);
            }

            float xwv = xw[i], ywv = yw[i];
            float wa = (1.0f - xwv) * (1.0f - ywv);
            float wb = (1.0f - xwv) * ywv;
            float wc = xwv * (1.0f - ywv);
            float wd = xwv * ywv;

            float r = wa * Ia;
            r = fmaf(wb, Ib, r);
            r = fmaf(wc, Ic, r);
            r = fmaf(wd, Id, r);
            oplane[(h0 + i) * W_ + w] = r;
        }

        __syncthreads();                    // all reads of tile[c&1] done before
                                            // iter c+1 prefetches c+2 into it
    }
}

extern "C" void kernel_launch(void* const* d_in, const int* in_sizes, int n_in,
                              void* d_out, int out_size)
{
    const float* img = (const float*)d_in[0];
    const float* flo = (const float*)d_in[1];
    float* out = (float*)d_out;

    cudaFuncSetAttribute(warp_bilinear_kernel,
                         cudaFuncAttributeMaxDynamicSharedMemorySize, SMEM_BYTES);

    const int blocks = B_ * (H_ / TY);   // 512
    warp_bilinear_kernel<<<blocks, THREADS, SMEM_BYTES>>>(img, flo, out);
}